// round 6
// baseline (speedup 1.0000x reference)
#include <cuda_runtime.h>
#include <cuda_bf16.h>
#include <math.h>

#define BB 4096
#define IN_DIM 64
#define UU 256
#define NN 128
#define WW 64
#define OUT_DIM 64
#define NPH 70
#define PDIM 268   // 2*NPH + 2*W
#define CLIPV 20.0f
#define EPSV 1e-12f

// d_out layout (reference tuple order, each flattened):
#define O_OUT 0
#define O_RV  (BB*OUT_DIM)
#define O_WR  (O_RV + BB*WW)
#define O_WW  (O_WR + BB*NN)
#define O_M   (O_WW + BB*NN)
#define O_H   (O_M + (size_t)BB*NN*WW)
#define O_C   (O_H + (size_t)BB*UU)

__device__ float g_params[BB * PDIM];          // clipped head params
__device__ float g_z[(size_t)BB * 1024];       // raw LSTM pre-activations

__device__ __forceinline__ float sigf(float x) { return 1.0f / (1.0f + expf(-x)); }
__device__ __forceinline__ float softplusf(float x) { return log1pf(expf(x)); }
__device__ __forceinline__ float clipf(float x) { return fminf(fmaxf(x, -CLIPV), CLIPV); }

__device__ __forceinline__ void mma16816(float* c, const unsigned* a,
                                         unsigned b0, unsigned b1) {
    asm volatile(
        "mma.sync.aligned.m16n8k16.row.col.f32.bf16.bf16.f32 "
        "{%0,%1,%2,%3}, {%4,%5,%6,%7}, {%8,%9}, {%0,%1,%2,%3};"
        : "+f"(c[0]), "+f"(c[1]), "+f"(c[2]), "+f"(c[3])
        : "r"(a[0]), "r"(a[1]), "r"(a[2]), "r"(a[3]), "r"(b0), "r"(b1));
}

// ---------------------------------------------------------------------------
// K1: z = [x,rv0,h0] @ [Wk;Wr]  -> g_z   (bf16 3-pass split MMA, fp32 accum)
// CTA tile 128x128, 8 warps (2x4), each warp 64x32 via 4x4 m16n8k16 tiles.
// K=384 in 16-steps; per step 3 phases: Ah*Wh, Ah*Wl, Al*Wh.
// ---------------------------------------------------------------------------
#define LDK 24   // padded bf16 k-stride (conflict-free fragment loads)

__global__ __launch_bounds__(256) void k1_gemm(
    const float* __restrict__ x, const float* __restrict__ rv0,
    const float* __restrict__ h0,
    const float* __restrict__ Wk, const float* __restrict__ Wr)
{
    __shared__ __nv_bfloat16 Ah[128 * LDK], Al[128 * LDK];
    __shared__ __nv_bfloat16 Bh[128 * LDK], Bl[128 * LDK];

    const int tid = threadIdx.x;
    const int m0 = blockIdx.x * 128, n0 = blockIdx.y * 128;
    const int lane = tid & 31, wid = tid >> 5;
    const int wm = wid & 1, wn = wid >> 1;   // warp tile: (wm*64 rows, wn*32 cols)
    const int g = lane >> 2, t = lane & 3;

    float acc[4][4][4];
#pragma unroll
    for (int mi = 0; mi < 4; mi++)
#pragma unroll
        for (int nj = 0; nj < 4; nj++)
#pragma unroll
            for (int q = 0; q < 4; q++) acc[mi][nj][q] = 0.0f;

    float av[8], wv[8];

    auto loadA = [&](int kb) {
#pragma unroll
        for (int e = 0; e < 8; e++) {
            int idx = tid + e * 256;
            int row = m0 + (idx >> 4);
            int kk = kb + (idx & 15);
            float v;
            if (kk < 64)       v = x[row * 64 + kk];
            else if (kk < 128) v = rv0[row * 64 + (kk - 64)];
            else               v = h0[row * 256 + (kk - 128)];
            av[e] = v;
        }
    };
    auto loadW = [&](int kb) {
#pragma unroll
        for (int e = 0; e < 8; e++) {
            int idx = tid + e * 256;
            int kk = kb + (idx >> 7);
            int col = n0 + (idx & 127);
            wv[e] = (kk < 128) ? Wk[kk * 1024 + col] : Wr[(kk - 128) * 1024 + col];
        }
    };
    auto storeA = [&]() {
#pragma unroll
        for (int e = 0; e < 8; e++) {
            int idx = tid + e * 256;
            int row = idx >> 4, kk = idx & 15;
            float v = av[e];
            __nv_bfloat16 hi = __float2bfloat16(v);
            Ah[row * LDK + kk] = hi;
            Al[row * LDK + kk] = __float2bfloat16(v - __bfloat162float(hi));
        }
    };
    auto storeW = [&]() {
#pragma unroll
        for (int e = 0; e < 8; e++) {
            int idx = tid + e * 256;
            int kk = idx >> 7, nn = idx & 127;
            float v = wv[e];
            __nv_bfloat16 hi = __float2bfloat16(v);
            Bh[nn * LDK + kk] = hi;
            Bl[nn * LDK + kk] = __float2bfloat16(v - __bfloat162float(hi));
        }
    };

    loadA(0); loadW(0);

    for (int it = 0; it < 24; it++) {
        __syncthreads();                 // previous compute done with smem
        storeA(); storeW();
        __syncthreads();
        if (it < 23) { loadA(16 * (it + 1)); loadW(16 * (it + 1)); }  // overlap w/ compute

        unsigned af[4][4];
        // phase 0+1: A-hi fragments
#pragma unroll
        for (int mi = 0; mi < 4; mi++) {
            int rb = wm * 64 + mi * 16;
            af[mi][0] = *(const unsigned*)&Ah[(rb + g) * LDK + 2 * t];
            af[mi][1] = *(const unsigned*)&Ah[(rb + g + 8) * LDK + 2 * t];
            af[mi][2] = *(const unsigned*)&Ah[(rb + g) * LDK + 2 * t + 8];
            af[mi][3] = *(const unsigned*)&Ah[(rb + g + 8) * LDK + 2 * t + 8];
        }
#pragma unroll
        for (int nj = 0; nj < 4; nj++) {        // Ah * Wh
            int cb = wn * 32 + nj * 8 + g;
            unsigned b0 = *(const unsigned*)&Bh[cb * LDK + 2 * t];
            unsigned b1 = *(const unsigned*)&Bh[cb * LDK + 2 * t + 8];
#pragma unroll
            for (int mi = 0; mi < 4; mi++) mma16816(acc[mi][nj], af[mi], b0, b1);
        }
#pragma unroll
        for (int nj = 0; nj < 4; nj++) {        // Ah * Wl
            int cb = wn * 32 + nj * 8 + g;
            unsigned b0 = *(const unsigned*)&Bl[cb * LDK + 2 * t];
            unsigned b1 = *(const unsigned*)&Bl[cb * LDK + 2 * t + 8];
#pragma unroll
            for (int mi = 0; mi < 4; mi++) mma16816(acc[mi][nj], af[mi], b0, b1);
        }
        // phase 2: A-lo * Wh
#pragma unroll
        for (int mi = 0; mi < 4; mi++) {
            int rb = wm * 64 + mi * 16;
            af[mi][0] = *(const unsigned*)&Al[(rb + g) * LDK + 2 * t];
            af[mi][1] = *(const unsigned*)&Al[(rb + g + 8) * LDK + 2 * t];
            af[mi][2] = *(const unsigned*)&Al[(rb + g) * LDK + 2 * t + 8];
            af[mi][3] = *(const unsigned*)&Al[(rb + g + 8) * LDK + 2 * t + 8];
        }
#pragma unroll
        for (int nj = 0; nj < 4; nj++) {
            int cb = wn * 32 + nj * 8 + g;
            unsigned b0 = *(const unsigned*)&Bh[cb * LDK + 2 * t];
            unsigned b1 = *(const unsigned*)&Bh[cb * LDK + 2 * t + 8];
#pragma unroll
            for (int mi = 0; mi < 4; mi++) mma16816(acc[mi][nj], af[mi], b0, b1);
        }
    }

    // store z (fragment layout: c0,c1 @ (row, col..col+1); c2,c3 @ row+8)
#pragma unroll
    for (int mi = 0; mi < 4; mi++)
#pragma unroll
        for (int nj = 0; nj < 4; nj++) {
            int row = m0 + wm * 64 + mi * 16 + g;
            int col = n0 + wn * 32 + nj * 8 + 2 * t;
            *(float2*)&g_z[(size_t)row * 1024 + col] =
                make_float2(acc[mi][nj][0], acc[mi][nj][1]);
            *(float2*)&g_z[(size_t)(row + 8) * 1024 + col] =
                make_float2(acc[mi][nj][2], acc[mi][nj][3]);
        }
}

// ---------------------------------------------------------------------------
// K2: LSTM gate epilogue (from g_z) -> h_new/c_new, then
//     params = clip(h_new @ W_p + b_p) -> g_params.  16 rows/CTA.
// ---------------------------------------------------------------------------
__global__ __launch_bounds__(288) void k2_params(
    const float* __restrict__ c0, const float* __restrict__ bl,
    const float* __restrict__ Wp, const float* __restrict__ bp,
    float* __restrict__ out)
{
    __shared__ float hs[16 * 256];
    int row0 = blockIdx.x * 16;
    int tid = threadIdx.x;

    for (int i = tid; i < 16 * 256; i += 288) {
        int r = i >> 8, u = i & 255;
        int row = row0 + r;
        const float* zr = g_z + (size_t)row * 1024 + u;
        float zi = zr[0]   + bl[u];
        float zf = zr[256] + bl[256 + u];
        float zg = zr[512] + bl[512 + u];
        float zo = zr[768] + bl[768 + u];
        float cn = sigf(zf) * c0[row * 256 + u] + sigf(zi) * tanhf(zg);
        float hn = sigf(zo) * tanhf(cn);
        out[O_C + (size_t)row * 256 + u] = cn;
        out[O_H + (size_t)row * 256 + u] = hn;
        hs[i] = hn;
    }
    __syncthreads();

    int c = tid;
    if (c < PDIM) {
        float acc[16];
#pragma unroll
        for (int j = 0; j < 16; j++) acc[j] = 0.0f;
        for (int k = 0; k < 256; k += 4) {
            float w0 = Wp[(k + 0) * PDIM + c];
            float w1 = Wp[(k + 1) * PDIM + c];
            float w2 = Wp[(k + 2) * PDIM + c];
            float w3 = Wp[(k + 3) * PDIM + c];
#pragma unroll
            for (int j = 0; j < 16; j++) {
                float4 h4 = *(const float4*)&hs[j * 256 + k];
                acc[j] += h4.x * w0 + h4.y * w1 + h4.z * w2 + h4.w * w3;
            }
        }
        float b = bp[c];
#pragma unroll
        for (int j = 0; j < 16; j++)
            g_params[(row0 + j) * PDIM + c] = clipf(acc[j] + b);
    }
}

// ---------------------------------------------------------------------------
// K3: per-sample addressing (2 heads) + read_vec + memory update.
// ---------------------------------------------------------------------------
__global__ __launch_bounds__(128) void k3_addr(
    const float* __restrict__ M,
    const float* __restrict__ w0p, const float* __restrict__ w1p,
    float* __restrict__ out)
{
    __shared__ float Ms[128 * 65];
    __shared__ float psm[PDIM];
    __shared__ float ks[64], er[64], ad[64];
    __shared__ float wgs[128], wrs[128], wws[128];
    __shared__ float red[4];
    __shared__ float part[128];

    int b = blockIdx.x, tid = threadIdx.x;
    int lane = tid & 31, wid = tid >> 5;

    const float4* M4 = (const float4*)(M + (size_t)b * NN * WW);
#pragma unroll
    for (int t = 0; t < 16; t++) {
        int idx4 = tid + t * 128;
        float4 v = M4[idx4];
        int n = idx4 >> 4, w0 = (idx4 & 15) * 4;
        float* p = &Ms[n * 65 + w0];
        p[0] = v.x; p[1] = v.y; p[2] = v.z; p[3] = v.w;
    }
    for (int i = tid; i < PDIM; i += 128) psm[i] = g_params[b * PDIM + i];
    __syncthreads();

    float s = 0.0f;
#pragma unroll
    for (int w = 0; w < 64; w++) { float m = Ms[tid * 65 + w]; s += m * m; }
    float minv = rsqrtf(fmaxf(s, EPSV));

    if (tid < 64) {
        er[tid] = sigf(psm[2 * NPH + tid]);
        ad[tid] = tanhf(psm[2 * NPH + WW + tid]);
    }

    for (int h = 0; h < 2; h++) {
        int off = h * NPH;
        if (tid < 64) ks[tid] = tanhf(psm[off + tid]);
        __syncthreads();

        float sk = 0.0f;
#pragma unroll
        for (int w = 0; w < 64; w++) sk += ks[w] * ks[w];
        float kninv = rsqrtf(fmaxf(sk, EPSV));
        float beta = softplusf(psm[off + 64]);
        float g = sigf(psm[off + 65]);
        float e0 = psm[off + 66], e1 = psm[off + 67], e2 = psm[off + 68];
        float mx3 = fmaxf(e0, fmaxf(e1, e2));
        float x0 = expf(e0 - mx3), x1 = expf(e1 - mx3), x2 = expf(e2 - mx3);
        float sinv = 1.0f / (x0 + x1 + x2);
        float s0 = x0 * sinv, s1 = x1 * sinv, s2 = x2 * sinv;
        float gamma = softplusf(psm[off + 69]) + 1.0f;

        float dot = 0.0f;
#pragma unroll
        for (int w = 0; w < 64; w++) dot += ks[w] * Ms[tid * 65 + w];
        float v = beta * (-dot * kninv * minv);

        float m = v;
#pragma unroll
        for (int o = 16; o; o >>= 1) m = fmaxf(m, __shfl_xor_sync(0xffffffffu, m, o));
        if (lane == 0) red[wid] = m;
        __syncthreads();
        m = fmaxf(fmaxf(red[0], red[1]), fmaxf(red[2], red[3]));
        float e = expf(v - m);
        float ssum = e;
#pragma unroll
        for (int o = 16; o; o >>= 1) ssum += __shfl_xor_sync(0xffffffffu, ssum, o);
        __syncthreads();
        if (lane == 0) red[wid] = ssum;
        __syncthreads();
        ssum = red[0] + red[1] + red[2] + red[3];
        float wc = e / ssum;

        const float* prev = h ? w1p : w0p;
        float wg = g * wc + (1.0f - g) * prev[b * 128 + tid];
        wgs[tid] = wg;
        __syncthreads();

        float w_ = s0 * wg + s1 * wgs[(tid + 127) & 127] + s2 * wgs[(tid + 1) & 127];
        float wsh = exp2f(gamma * log2f(w_));   // w_ >= 0; w_==0 -> 0 (was powf)
        float s2sum = wsh;
#pragma unroll
        for (int o = 16; o; o >>= 1) s2sum += __shfl_xor_sync(0xffffffffu, s2sum, o);
        __syncthreads();
        if (lane == 0) red[wid] = s2sum;
        __syncthreads();
        s2sum = red[0] + red[1] + red[2] + red[3];
        float wf = wsh / s2sum;

        if (h == 0) { wrs[tid] = wf; out[O_WR + (size_t)b * 128 + tid] = wf; }
        else        { wws[tid] = wf; out[O_WW + (size_t)b * 128 + tid] = wf; }
        __syncthreads();
    }

    {
        int w = tid & 63, half = tid >> 6;
        float r = 0.0f;
#pragma unroll
        for (int i = 0; i < 64; i++) {
            int n = half * 64 + i;
            r += wrs[n] * Ms[n * 65 + w];
        }
        part[half * 64 + w] = r;
        __syncthreads();
        if (tid < 64) out[O_RV + (size_t)b * 64 + tid] = part[tid] + part[64 + tid];
    }

    float4* Mo = (float4*)(out + O_M + (size_t)b * NN * WW);
#pragma unroll
    for (int t = 0; t < 16; t++) {
        int idx4 = tid + t * 128;
        int n = idx4 >> 4, w0 = (idx4 & 15) * 4;
        float wn = wws[n];
        const float* p = &Ms[n * 65 + w0];
        float4 v;
        v.x = p[0] * (1.0f - wn * er[w0 + 0]) + wn * ad[w0 + 0];
        v.y = p[1] * (1.0f - wn * er[w0 + 1]) + wn * ad[w0 + 1];
        v.z = p[2] * (1.0f - wn * er[w0 + 2]) + wn * ad[w0 + 2];
        v.w = p[3] * (1.0f - wn * er[w0 + 3]) + wn * ad[w0 + 3];
        Mo[idx4] = v;
    }
}

// ---------------------------------------------------------------------------
// K4: out = clip([h_new, read_vec] @ W_o + b_o).
// 16 rows/CTA, 256 threads: 64 cols x 4 k-quarters (split-k), smem reduce.
// ---------------------------------------------------------------------------
__global__ __launch_bounds__(256) void k4_out(
    const float* __restrict__ Wo, const float* __restrict__ bo,
    float* __restrict__ out)
{
    __shared__ float hs[16 * 320];
    __shared__ float red[4][16 * 64];
    int tid = threadIdx.x;
    int row0 = blockIdx.x * 16;

    for (int i = tid; i < 16 * 320; i += 256) {
        int r = i / 320, k = i - r * 320;
        hs[i] = (k < 256) ? out[O_H + (size_t)(row0 + r) * 256 + k]
                          : out[O_RV + (size_t)(row0 + r) * 64 + (k - 256)];
    }
    __syncthreads();

    int c = tid & 63, kq = tid >> 6;
    float acc[16];
#pragma unroll
    for (int j = 0; j < 16; j++) acc[j] = 0.0f;

    int kbeg = kq * 80;
    for (int k = kbeg; k < kbeg + 80; k += 4) {
        float w0 = Wo[(k + 0) * 64 + c];
        float w1 = Wo[(k + 1) * 64 + c];
        float w2 = Wo[(k + 2) * 64 + c];
        float w3 = Wo[(k + 3) * 64 + c];
#pragma unroll
        for (int j = 0; j < 16; j++) {
            float4 h4 = *(const float4*)&hs[j * 320 + k];
            acc[j] += h4.x * w0 + h4.y * w1 + h4.z * w2 + h4.w * w3;
        }
    }
#pragma unroll
    for (int j = 0; j < 16; j++) red[kq][j * 64 + c] = acc[j];
    __syncthreads();

#pragma unroll
    for (int j = kq * 4; j < kq * 4 + 4; j++) {
        float sres = red[0][j * 64 + c] + red[1][j * 64 + c]
                   + red[2][j * 64 + c] + red[3][j * 64 + c];
        out[O_OUT + (size_t)(row0 + j) * 64 + c] = clipf(sres + bo[c]);
    }
}

// ---------------------------------------------------------------------------
extern "C" void kernel_launch(void* const* d_in, const int* in_sizes, int n_in,
                              void* d_out, int out_size)
{
    const float* x   = (const float*)d_in[0];
    const float* h0  = (const float*)d_in[1];
    const float* c0  = (const float*)d_in[2];
    const float* rv0 = (const float*)d_in[3];
    const float* w0p = (const float*)d_in[4];
    const float* w1p = (const float*)d_in[5];
    const float* M   = (const float*)d_in[6];
    const float* Wk  = (const float*)d_in[7];
    const float* Wr  = (const float*)d_in[8];
    const float* bl  = (const float*)d_in[9];
    const float* Wp  = (const float*)d_in[10];
    const float* bp  = (const float*)d_in[11];
    const float* Wo  = (const float*)d_in[12];
    const float* bo  = (const float*)d_in[13];
    float* out = (float*)d_out;

    k1_gemm<<<dim3(32, 8), 256>>>(x, rv0, h0, Wk, Wr);
    k2_params<<<BB / 16, 288>>>(c0, bl, Wp, bp, out);
    k3_addr<<<BB, 128>>>(M, w0p, w1p, out);
    k4_out<<<BB / 16, 256>>>(Wo, bo, out);
}

// round 7
// speedup vs baseline: 1.1918x; 1.1918x over previous
#include <cuda_runtime.h>
#include <cuda_bf16.h>
#include <math.h>

#define BB 4096
#define IN_DIM 64
#define UU 256
#define NN 128
#define WW 64
#define OUT_DIM 64
#define NPH 70
#define PDIM 268   // 2*NPH + 2*W
#define CLIPV 20.0f
#define EPSV 1e-12f
#define KD 384     // GEMM1 K dim

// d_out layout (reference tuple order, each flattened):
#define O_OUT 0
#define O_RV  (BB*OUT_DIM)
#define O_WR  (O_RV + BB*WW)
#define O_WW  (O_WR + BB*NN)
#define O_M   (O_WW + BB*NN)
#define O_H   (O_M + (size_t)BB*NN*WW)
#define O_C   (O_H + (size_t)BB*UU)

__device__ float g_params[BB * PDIM];               // clipped head params
__device__ float g_z[(size_t)BB * 1024];            // raw LSTM pre-activations
__device__ __nv_bfloat16 g_Ah[BB * KD], g_Al[BB * KD];      // activations hi/lo
__device__ __nv_bfloat16 g_Wh[1024 * KD], g_Wl[1024 * KD];  // weights^T hi/lo

__device__ __forceinline__ float sigf(float x) { return 1.0f / (1.0f + expf(-x)); }
__device__ __forceinline__ float softplusf(float x) { return log1pf(expf(x)); }
__device__ __forceinline__ float clipf(float x) { return fminf(fmaxf(x, -CLIPV), CLIPV); }

__device__ __forceinline__ void mma16816(float* c, const unsigned* a,
                                         unsigned b0, unsigned b1) {
    asm volatile(
        "mma.sync.aligned.m16n8k16.row.col.f32.bf16.bf16.f32 "
        "{%0,%1,%2,%3}, {%4,%5,%6,%7}, {%8,%9}, {%0,%1,%2,%3};"
        : "+f"(c[0]), "+f"(c[1]), "+f"(c[2]), "+f"(c[3])
        : "r"(a[0]), "r"(a[1]), "r"(a[2]), "r"(a[3]), "r"(b0), "r"(b1));
}

__device__ __forceinline__ void cp16(void* dst_smem, const void* src_gmem) {
    unsigned d = (unsigned)__cvta_generic_to_shared(dst_smem);
    asm volatile("cp.async.cg.shared.global [%0], [%1], 16;\n" :: "r"(d), "l"(src_gmem));
}
#define CP_COMMIT() asm volatile("cp.async.commit_group;\n" ::: "memory")
#define CP_WAIT(n)  asm volatile("cp.async.wait_group %0;\n" :: "n"(n) : "memory")

// ---------------------------------------------------------------------------
// K0a: convert activations [x | rv0 | h0] -> g_Ah/g_Al (bf16 hi + residual lo)
// ---------------------------------------------------------------------------
__global__ __launch_bounds__(1024) void k0_act(
    const float* __restrict__ x, const float* __restrict__ rv0,
    const float* __restrict__ h0)
{
    int idx = blockIdx.x * 1024 + threadIdx.x;   // row*384 + kk
    int row = idx / KD, kk = idx - row * KD;
    float v;
    if (kk < 64)       v = x[row * 64 + kk];
    else if (kk < 128) v = rv0[row * 64 + (kk - 64)];
    else               v = h0[row * 256 + (kk - 128)];
    __nv_bfloat16 hi = __float2bfloat16(v);
    g_Ah[idx] = hi;
    g_Al[idx] = __float2bfloat16(v - __bfloat162float(hi));
}

// ---------------------------------------------------------------------------
// K0b: transpose + convert weights [Wk;Wr] (384x1024) -> g_Wh/g_Wl [1024][384]
// ---------------------------------------------------------------------------
__global__ __launch_bounds__(256) void k0_wt(
    const float* __restrict__ Wk, const float* __restrict__ Wr)
{
    __shared__ float t[32][33];
    int n0 = blockIdx.x * 32, k0 = blockIdx.y * 32;
    int tx = threadIdx.x & 31, ty = threadIdx.x >> 5;   // 32 x 8
#pragma unroll
    for (int i = 0; i < 32; i += 8) {
        int k = k0 + ty + i, n = n0 + tx;
        t[ty + i][tx] = (k < 128) ? Wk[k * 1024 + n] : Wr[(k - 128) * 1024 + n];
    }
    __syncthreads();
#pragma unroll
    for (int i = 0; i < 32; i += 8) {
        int n = n0 + ty + i, k = k0 + tx;
        float v = t[tx][ty + i];
        __nv_bfloat16 hi = __float2bfloat16(v);
        g_Wh[n * KD + k] = hi;
        g_Wl[n * KD + k] = __float2bfloat16(v - __bfloat162float(hi));
    }
}

// ---------------------------------------------------------------------------
// K1: z = A @ W^T -> g_z.  bf16 3-pass split MMA (Ah*Wh + Ah*Wl + Al*Wh).
// CTA 128x128, 8 warps (2x4), warp 64x32 via 4x4 m16n8k16.
// K chunks of 16, cp.async double-buffered. smem: 2 stages x 4 bufs x 6KB = 48KB.
// ---------------------------------------------------------------------------
#define LDK 24   // padded bf16 k-stride: fragment bank = (12g+t)%32, a permutation

__global__ __launch_bounds__(256, 2) void k1_gemm()
{
    __shared__ __nv_bfloat16 smem[2 * 4 * 128 * LDK];   // 48KB
    const int tid = threadIdx.x;
    const int m0 = blockIdx.x * 128, n0 = blockIdx.y * 128;
    const int lane = tid & 31, wid = tid >> 5;
    const int wm = wid & 1, wn = wid >> 1;
    const int g = lane >> 2, t = lane & 3;

    float acc[4][4][4];
#pragma unroll
    for (int mi = 0; mi < 4; mi++)
#pragma unroll
        for (int nj = 0; nj < 4; nj++)
#pragma unroll
            for (int q = 0; q < 4; q++) acc[mi][nj][q] = 0.0f;

    const int row = tid >> 1, seg = tid & 1;       // cp.async mapping
    const int soff = row * LDK + seg * 8;          // halves
    const int goffA = (m0 + row) * KD + seg * 8;
    const int goffB = (n0 + row) * KD + seg * 8;

    auto issue = [&](int s, int kb) {
        __nv_bfloat16* base = smem + s * (4 * 128 * LDK);
        cp16(base + 0 * 128 * LDK + soff, g_Ah + goffA + kb);
        cp16(base + 1 * 128 * LDK + soff, g_Al + goffA + kb);
        cp16(base + 2 * 128 * LDK + soff, g_Wh + goffB + kb);
        cp16(base + 3 * 128 * LDK + soff, g_Wl + goffB + kb);
        CP_COMMIT();
    };

    issue(0, 0);

    for (int it = 0; it < 24; it++) {
        if (it < 23) { issue((it + 1) & 1, 16 * (it + 1)); CP_WAIT(1); }
        else         { CP_WAIT(0); }
        __syncthreads();

        const __nv_bfloat16* Ah = smem + (it & 1) * (4 * 128 * LDK);
        const __nv_bfloat16* Al = Ah + 128 * LDK;
        const __nv_bfloat16* Bh = Ah + 2 * 128 * LDK;
        const __nv_bfloat16* Bl = Ah + 3 * 128 * LDK;

        unsigned af[4][4];
#pragma unroll
        for (int mi = 0; mi < 4; mi++) {
            int rb = wm * 64 + mi * 16;
            af[mi][0] = *(const unsigned*)&Ah[(rb + g) * LDK + 2 * t];
            af[mi][1] = *(const unsigned*)&Ah[(rb + g + 8) * LDK + 2 * t];
            af[mi][2] = *(const unsigned*)&Ah[(rb + g) * LDK + 2 * t + 8];
            af[mi][3] = *(const unsigned*)&Ah[(rb + g + 8) * LDK + 2 * t + 8];
        }
#pragma unroll
        for (int nj = 0; nj < 4; nj++) {            // Ah * Wh
            int cb = wn * 32 + nj * 8 + g;
            unsigned b0 = *(const unsigned*)&Bh[cb * LDK + 2 * t];
            unsigned b1 = *(const unsigned*)&Bh[cb * LDK + 2 * t + 8];
#pragma unroll
            for (int mi = 0; mi < 4; mi++) mma16816(acc[mi][nj], af[mi], b0, b1);
        }
#pragma unroll
        for (int nj = 0; nj < 4; nj++) {            // Ah * Wl
            int cb = wn * 32 + nj * 8 + g;
            unsigned b0 = *(const unsigned*)&Bl[cb * LDK + 2 * t];
            unsigned b1 = *(const unsigned*)&Bl[cb * LDK + 2 * t + 8];
#pragma unroll
            for (int mi = 0; mi < 4; mi++) mma16816(acc[mi][nj], af[mi], b0, b1);
        }
#pragma unroll
        for (int mi = 0; mi < 4; mi++) {            // Al fragments
            int rb = wm * 64 + mi * 16;
            af[mi][0] = *(const unsigned*)&Al[(rb + g) * LDK + 2 * t];
            af[mi][1] = *(const unsigned*)&Al[(rb + g + 8) * LDK + 2 * t];
            af[mi][2] = *(const unsigned*)&Al[(rb + g) * LDK + 2 * t + 8];
            af[mi][3] = *(const unsigned*)&Al[(rb + g + 8) * LDK + 2 * t + 8];
        }
#pragma unroll
        for (int nj = 0; nj < 4; nj++) {            // Al * Wh
            int cb = wn * 32 + nj * 8 + g;
            unsigned b0 = *(const unsigned*)&Bh[cb * LDK + 2 * t];
            unsigned b1 = *(const unsigned*)&Bh[cb * LDK + 2 * t + 8];
#pragma unroll
            for (int mi = 0; mi < 4; mi++) mma16816(acc[mi][nj], af[mi], b0, b1);
        }
        __syncthreads();    // buf reused by cp.async two iterations later
    }

#pragma unroll
    for (int mi = 0; mi < 4; mi++)
#pragma unroll
        for (int nj = 0; nj < 4; nj++) {
            int r = m0 + wm * 64 + mi * 16 + g;
            int col = n0 + wn * 32 + nj * 8 + 2 * t;
            *(float2*)&g_z[(size_t)r * 1024 + col] =
                make_float2(acc[mi][nj][0], acc[mi][nj][1]);
            *(float2*)&g_z[(size_t)(r + 8) * 1024 + col] =
                make_float2(acc[mi][nj][2], acc[mi][nj][3]);
        }
}

// ---------------------------------------------------------------------------
// K2: LSTM gate epilogue (from g_z) -> h_new/c_new, then
//     params = clip(h_new @ W_p + b_p) -> g_params.  16 rows/CTA.
// ---------------------------------------------------------------------------
__global__ __launch_bounds__(288) void k2_params(
    const float* __restrict__ c0, const float* __restrict__ bl,
    const float* __restrict__ Wp, const float* __restrict__ bp,
    float* __restrict__ out)
{
    __shared__ float hs[16 * 256];
    int row0 = blockIdx.x * 16;
    int tid = threadIdx.x;

    for (int i = tid; i < 16 * 256; i += 288) {
        int r = i >> 8, u = i & 255;
        int row = row0 + r;
        const float* zr = g_z + (size_t)row * 1024 + u;
        float zi = zr[0]   + bl[u];
        float zf = zr[256] + bl[256 + u];
        float zg = zr[512] + bl[512 + u];
        float zo = zr[768] + bl[768 + u];
        float cn = sigf(zf) * c0[row * 256 + u] + sigf(zi) * tanhf(zg);
        float hn = sigf(zo) * tanhf(cn);
        out[O_C + (size_t)row * 256 + u] = cn;
        out[O_H + (size_t)row * 256 + u] = hn;
        hs[i] = hn;
    }
    __syncthreads();

    int c = tid;
    if (c < PDIM) {
        float acc[16];
#pragma unroll
        for (int j = 0; j < 16; j++) acc[j] = 0.0f;
        for (int k = 0; k < 256; k += 4) {
            float w0 = Wp[(k + 0) * PDIM + c];
            float w1 = Wp[(k + 1) * PDIM + c];
            float w2 = Wp[(k + 2) * PDIM + c];
            float w3 = Wp[(k + 3) * PDIM + c];
#pragma unroll
            for (int j = 0; j < 16; j++) {
                float4 h4 = *(const float4*)&hs[j * 256 + k];
                acc[j] += h4.x * w0 + h4.y * w1 + h4.z * w2 + h4.w * w3;
            }
        }
        float b = bp[c];
#pragma unroll
        for (int j = 0; j < 16; j++)
            g_params[(row0 + j) * PDIM + c] = clipf(acc[j] + b);
    }
}

// ---------------------------------------------------------------------------
// K3: per-sample addressing (2 heads) + read_vec + memory update.
// ---------------------------------------------------------------------------
__global__ __launch_bounds__(128) void k3_addr(
    const float* __restrict__ M,
    const float* __restrict__ w0p, const float* __restrict__ w1p,
    float* __restrict__ out)
{
    __shared__ float Ms[128 * 65];
    __shared__ float psm[PDIM];
    __shared__ float ks[64], er[64], ad[64];
    __shared__ float wgs[128], wrs[128], wws[128];
    __shared__ float red[4];
    __shared__ float part[128];

    int b = blockIdx.x, tid = threadIdx.x;
    int lane = tid & 31, wid = tid >> 5;

    const float4* M4 = (const float4*)(M + (size_t)b * NN * WW);
#pragma unroll
    for (int t = 0; t < 16; t++) {
        int idx4 = tid + t * 128;
        float4 v = M4[idx4];
        int n = idx4 >> 4, w0 = (idx4 & 15) * 4;
        float* p = &Ms[n * 65 + w0];
        p[0] = v.x; p[1] = v.y; p[2] = v.z; p[3] = v.w;
    }
    for (int i = tid; i < PDIM; i += 128) psm[i] = g_params[b * PDIM + i];
    __syncthreads();

    float s = 0.0f;
#pragma unroll
    for (int w = 0; w < 64; w++) { float m = Ms[tid * 65 + w]; s += m * m; }
    float minv = rsqrtf(fmaxf(s, EPSV));

    if (tid < 64) {
        er[tid] = sigf(psm[2 * NPH + tid]);
        ad[tid] = tanhf(psm[2 * NPH + WW + tid]);
    }

    for (int h = 0; h < 2; h++) {
        int off = h * NPH;
        if (tid < 64) ks[tid] = tanhf(psm[off + tid]);
        __syncthreads();

        float sk = 0.0f;
#pragma unroll
        for (int w = 0; w < 64; w++) sk += ks[w] * ks[w];
        float kninv = rsqrtf(fmaxf(sk, EPSV));
        float beta = softplusf(psm[off + 64]);
        float g = sigf(psm[off + 65]);
        float e0 = psm[off + 66], e1 = psm[off + 67], e2 = psm[off + 68];
        float mx3 = fmaxf(e0, fmaxf(e1, e2));
        float x0 = expf(e0 - mx3), x1 = expf(e1 - mx3), x2 = expf(e2 - mx3);
        float sinv = 1.0f / (x0 + x1 + x2);
        float s0 = x0 * sinv, s1 = x1 * sinv, s2 = x2 * sinv;
        float gamma = softplusf(psm[off + 69]) + 1.0f;

        float dot = 0.0f;
#pragma unroll
        for (int w = 0; w < 64; w++) dot += ks[w] * Ms[tid * 65 + w];
        float v = beta * (-dot * kninv * minv);

        float m = v;
#pragma unroll
        for (int o = 16; o; o >>= 1) m = fmaxf(m, __shfl_xor_sync(0xffffffffu, m, o));
        if (lane == 0) red[wid] = m;
        __syncthreads();
        m = fmaxf(fmaxf(red[0], red[1]), fmaxf(red[2], red[3]));
        float e = expf(v - m);
        float ssum = e;
#pragma unroll
        for (int o = 16; o; o >>= 1) ssum += __shfl_xor_sync(0xffffffffu, ssum, o);
        __syncthreads();
        if (lane == 0) red[wid] = ssum;
        __syncthreads();
        ssum = red[0] + red[1] + red[2] + red[3];
        float wc = e / ssum;

        const float* prev = h ? w1p : w0p;
        float wg = g * wc + (1.0f - g) * prev[b * 128 + tid];
        wgs[tid] = wg;
        __syncthreads();

        float w_ = s0 * wg + s1 * wgs[(tid + 127) & 127] + s2 * wgs[(tid + 1) & 127];
        float wsh = exp2f(gamma * log2f(w_));   // w_ >= 0; w_==0 -> 0
        float s2sum = wsh;
#pragma unroll
        for (int o = 16; o; o >>= 1) s2sum += __shfl_xor_sync(0xffffffffu, s2sum, o);
        __syncthreads();
        if (lane == 0) red[wid] = s2sum;
        __syncthreads();
        s2sum = red[0] + red[1] + red[2] + red[3];
        float wf = wsh / s2sum;

        if (h == 0) { wrs[tid] = wf; out[O_WR + (size_t)b * 128 + tid] = wf; }
        else        { wws[tid] = wf; out[O_WW + (size_t)b * 128 + tid] = wf; }
        __syncthreads();
    }

    {
        int w = tid & 63, half = tid >> 6;
        float r = 0.0f;
#pragma unroll
        for (int i = 0; i < 64; i++) {
            int n = half * 64 + i;
            r += wrs[n] * Ms[n * 65 + w];
        }
        part[half * 64 + w] = r;
        __syncthreads();
        if (tid < 64) out[O_RV + (size_t)b * 64 + tid] = part[tid] + part[64 + tid];
    }

    float4* Mo = (float4*)(out + O_M + (size_t)b * NN * WW);
#pragma unroll
    for (int t = 0; t < 16; t++) {
        int idx4 = tid + t * 128;
        int n = idx4 >> 4, w0 = (idx4 & 15) * 4;
        float wn = wws[n];
        const float* p = &Ms[n * 65 + w0];
        float4 v;
        v.x = p[0] * (1.0f - wn * er[w0 + 0]) + wn * ad[w0 + 0];
        v.y = p[1] * (1.0f - wn * er[w0 + 1]) + wn * ad[w0 + 1];
        v.z = p[2] * (1.0f - wn * er[w0 + 2]) + wn * ad[w0 + 2];
        v.w = p[3] * (1.0f - wn * er[w0 + 3]) + wn * ad[w0 + 3];
        Mo[idx4] = v;
    }
}

// ---------------------------------------------------------------------------
// K4: out = clip([h_new, read_vec] @ W_o + b_o).
// 8 rows/CTA, 256 threads: 64 cols x 4 k-quarters (split-k), smem reduce.
// ---------------------------------------------------------------------------
__global__ __launch_bounds__(256) void k4_out(
    const float* __restrict__ Wo, const float* __restrict__ bo,
    float* __restrict__ out)
{
    __shared__ float hs[8 * 320];
    __shared__ float red[4][8 * 64];
    int tid = threadIdx.x;
    int row0 = blockIdx.x * 8;

    for (int i = tid; i < 8 * 320; i += 256) {
        int r = i / 320, k = i - r * 320;
        hs[i] = (k < 256) ? out[O_H + (size_t)(row0 + r) * 256 + k]
                          : out[O_RV + (size_t)(row0 + r) * 64 + (k - 256)];
    }
    __syncthreads();

    int c = tid & 63, kq = tid >> 6;
    float acc[8];
#pragma unroll
    for (int j = 0; j < 8; j++) acc[j] = 0.0f;

    int kbeg = kq * 80;
    for (int k = kbeg; k < kbeg + 80; k += 4) {
        float w0 = Wo[(k + 0) * 64 + c];
        float w1 = Wo[(k + 1) * 64 + c];
        float w2 = Wo[(k + 2) * 64 + c];
        float w3 = Wo[(k + 3) * 64 + c];
#pragma unroll
        for (int j = 0; j < 8; j++) {
            float4 h4 = *(const float4*)&hs[j * 320 + k];
            acc[j] += h4.x * w0 + h4.y * w1 + h4.z * w2 + h4.w * w3;
        }
    }
#pragma unroll
    for (int j = 0; j < 8; j++) red[kq][j * 64 + c] = acc[j];
    __syncthreads();

#pragma unroll
    for (int j = kq * 2; j < kq * 2 + 2; j++) {
        float sres = red[0][j * 64 + c] + red[1][j * 64 + c]
                   + red[2][j * 64 + c] + red[3][j * 64 + c];
        out[O_OUT + (size_t)(row0 + j) * 64 + c] = clipf(sres + bo[c]);
    }
}

// ---------------------------------------------------------------------------
extern "C" void kernel_launch(void* const* d_in, const int* in_sizes, int n_in,
                              void* d_out, int out_size)
{
    const float* x   = (const float*)d_in[0];
    const float* h0  = (const float*)d_in[1];
    const float* c0  = (const float*)d_in[2];
    const float* rv0 = (const float*)d_in[3];
    const float* w0p = (const float*)d_in[4];
    const float* w1p = (const float*)d_in[5];
    const float* M   = (const float*)d_in[6];
    const float* Wk  = (const float*)d_in[7];
    const float* Wr  = (const float*)d_in[8];
    const float* bl  = (const float*)d_in[9];
    const float* Wp  = (const float*)d_in[10];
    const float* bp  = (const float*)d_in[11];
    const float* Wo  = (const float*)d_in[12];
    const float* bo  = (const float*)d_in[13];
    float* out = (float*)d_out;

    k0_act<<<BB * KD / 1024, 1024>>>(x, rv0, h0);
    k0_wt<<<dim3(32, 12), 256>>>(Wk, Wr);
    k1_gemm<<<dim3(32, 8), 256>>>();
    k2_params<<<BB / 16, 288>>>(c0, bl, Wp, bp, out);
    k3_addr<<<BB, 128>>>(M, w0p, w1p, out);
    k4_out<<<BB / 8, 256>>>(Wo, bo, out);
}

// round 9
// speedup vs baseline: 1.7577x; 1.4749x over previous
#include <cuda_runtime.h>
#include <cuda_bf16.h>
#include <math.h>

#define BB 4096
#define IN_DIM 64
#define UU 256
#define NN 128
#define WW 64
#define OUT_DIM 64
#define NPH 70
#define PDIM 268   // 2*NPH + 2*W
#define CLIPV 20.0f
#define EPSV 1e-12f
#define KD 384     // GEMM1 K dim

// d_out layout (reference tuple order, each flattened):
#define O_OUT 0
#define O_RV  (BB*OUT_DIM)
#define O_WR  (O_RV + BB*WW)
#define O_WW  (O_WR + BB*NN)
#define O_M   (O_WW + BB*NN)
#define O_H   (O_M + (size_t)BB*NN*WW)
#define O_C   (O_H + (size_t)BB*UU)

__device__ float g_params[BB * PDIM];               // clipped head params
__device__ float g_z[(size_t)BB * 1024];            // raw LSTM pre-activations
__device__ __nv_bfloat16 g_Ah[BB * KD], g_Al[BB * KD];      // activations hi/lo
__device__ __nv_bfloat16 g_Wh[1024 * KD], g_Wl[1024 * KD];  // weights^T hi/lo
__device__ __nv_bfloat16 g_Hh[BB * UU], g_Hl[BB * UU];      // h_new hi/lo
__device__ __nv_bfloat16 g_Wph[384 * UU], g_Wpl[384 * UU];  // Wp^T hi/lo (padded N)

__device__ __forceinline__ float sigf(float x) { return 1.0f / (1.0f + expf(-x)); }
__device__ __forceinline__ float softplusf(float x) { return log1pf(expf(x)); }
__device__ __forceinline__ float clipf(float x) { return fminf(fmaxf(x, -CLIPV), CLIPV); }

__device__ __forceinline__ void mma16816(float* c, const unsigned* a,
                                         unsigned b0, unsigned b1) {
    asm volatile(
        "mma.sync.aligned.m16n8k16.row.col.f32.bf16.bf16.f32 "
        "{%0,%1,%2,%3}, {%4,%5,%6,%7}, {%8,%9}, {%0,%1,%2,%3};"
        : "+f"(c[0]), "+f"(c[1]), "+f"(c[2]), "+f"(c[3])
        : "r"(a[0]), "r"(a[1]), "r"(a[2]), "r"(a[3]), "r"(b0), "r"(b1));
}

__device__ __forceinline__ void cp16(void* dst_smem, const void* src_gmem) {
    unsigned d = (unsigned)__cvta_generic_to_shared(dst_smem);
    asm volatile("cp.async.cg.shared.global [%0], [%1], 16;\n" :: "r"(d), "l"(src_gmem));
}
#define CP_COMMIT() asm volatile("cp.async.commit_group;\n" ::: "memory")
#define CP_WAIT(n)  asm volatile("cp.async.wait_group %0;\n" :: "n"(n) : "memory")

// ---------------------------------------------------------------------------
// K0a: convert activations [x | rv0 | h0] -> g_Ah/g_Al
// ---------------------------------------------------------------------------
__global__ __launch_bounds__(1024) void k0_act(
    const float* __restrict__ x, const float* __restrict__ rv0,
    const float* __restrict__ h0)
{
    int idx = blockIdx.x * 1024 + threadIdx.x;
    int row = idx / KD, kk = idx - row * KD;
    float v;
    if (kk < 64)       v = x[row * 64 + kk];
    else if (kk < 128) v = rv0[row * 64 + (kk - 64)];
    else               v = h0[row * 256 + (kk - 128)];
    __nv_bfloat16 hi = __float2bfloat16(v);
    g_Ah[idx] = hi;
    g_Al[idx] = __float2bfloat16(v - __bfloat162float(hi));
}

// ---------------------------------------------------------------------------
// K0b: transpose + convert [Wk;Wr] (384x1024) -> g_Wh/g_Wl [1024][384]
// ---------------------------------------------------------------------------
__global__ __launch_bounds__(256) void k0_wt(
    const float* __restrict__ Wk, const float* __restrict__ Wr)
{
    __shared__ float t[32][33];
    int n0 = blockIdx.x * 32, k0 = blockIdx.y * 32;
    int tx = threadIdx.x & 31, ty = threadIdx.x >> 5;
#pragma unroll
    for (int i = 0; i < 32; i += 8) {
        int k = k0 + ty + i, n = n0 + tx;
        t[ty + i][tx] = (k < 128) ? Wk[k * 1024 + n] : Wr[(k - 128) * 1024 + n];
    }
    __syncthreads();
#pragma unroll
    for (int i = 0; i < 32; i += 8) {
        int n = n0 + ty + i, k = k0 + tx;
        float v = t[tx][ty + i];
        __nv_bfloat16 hi = __float2bfloat16(v);
        g_Wh[n * KD + k] = hi;
        g_Wl[n * KD + k] = __float2bfloat16(v - __bfloat162float(hi));
    }
}

// ---------------------------------------------------------------------------
// K0c: transpose + convert Wp (256x268) -> g_Wph/g_Wpl [384][256] (zero-pad)
// ---------------------------------------------------------------------------
__global__ __launch_bounds__(256) void k0_wp(const float* __restrict__ Wp)
{
    __shared__ float t[32][33];
    int n0 = blockIdx.x * 32, k0 = blockIdx.y * 32;
    int tx = threadIdx.x & 31, ty = threadIdx.x >> 5;
#pragma unroll
    for (int i = 0; i < 32; i += 8) {
        int k = k0 + ty + i, n = n0 + tx;
        t[ty + i][tx] = (n < PDIM) ? Wp[k * PDIM + n] : 0.0f;
    }
    __syncthreads();
#pragma unroll
    for (int i = 0; i < 32; i += 8) {
        int n = n0 + ty + i, k = k0 + tx;
        float v = t[tx][ty + i];
        __nv_bfloat16 hi = __float2bfloat16(v);
        g_Wph[n * UU + k] = hi;
        g_Wpl[n * UU + k] = __float2bfloat16(v - __bfloat162float(hi));
    }
}

// ---------------------------------------------------------------------------
// K1: z = A @ W^T -> g_z.  bf16 3-pass split MMA, cp.async double-buffered.
// ---------------------------------------------------------------------------
#define LDK 24

__global__ __launch_bounds__(256, 2) void k1_gemm()
{
    __shared__ __nv_bfloat16 smem[2 * 4 * 128 * LDK];   // 48KB
    const int tid = threadIdx.x;
    const int m0 = blockIdx.x * 128, n0 = blockIdx.y * 128;
    const int lane = tid & 31, wid = tid >> 5;
    const int wm = wid & 1, wn = wid >> 1;
    const int g = lane >> 2, t = lane & 3;

    float acc[4][4][4];
#pragma unroll
    for (int mi = 0; mi < 4; mi++)
#pragma unroll
        for (int nj = 0; nj < 4; nj++)
#pragma unroll
            for (int q = 0; q < 4; q++) acc[mi][nj][q] = 0.0f;

    const int row = tid >> 1, seg = tid & 1;
    const int soff = row * LDK + seg * 8;
    const int goffA = (m0 + row) * KD + seg * 8;
    const int goffB = (n0 + row) * KD + seg * 8;

    auto issue = [&](int s, int kb) {
        __nv_bfloat16* base = smem + s * (4 * 128 * LDK);
        cp16(base + 0 * 128 * LDK + soff, g_Ah + goffA + kb);
        cp16(base + 1 * 128 * LDK + soff, g_Al + goffA + kb);
        cp16(base + 2 * 128 * LDK + soff, g_Wh + goffB + kb);
        cp16(base + 3 * 128 * LDK + soff, g_Wl + goffB + kb);
        CP_COMMIT();
    };

    issue(0, 0);

    for (int it = 0; it < 24; it++) {
        if (it < 23) { issue((it + 1) & 1, 16 * (it + 1)); CP_WAIT(1); }
        else         { CP_WAIT(0); }
        __syncthreads();

        const __nv_bfloat16* Ah = smem + (it & 1) * (4 * 128 * LDK);
        const __nv_bfloat16* Al = Ah + 128 * LDK;
        const __nv_bfloat16* Bh = Ah + 2 * 128 * LDK;
        const __nv_bfloat16* Bl = Ah + 3 * 128 * LDK;

        unsigned af[4][4];
#pragma unroll
        for (int mi = 0; mi < 4; mi++) {
            int rb = wm * 64 + mi * 16;
            af[mi][0] = *(const unsigned*)&Ah[(rb + g) * LDK + 2 * t];
            af[mi][1] = *(const unsigned*)&Ah[(rb + g + 8) * LDK + 2 * t];
            af[mi][2] = *(const unsigned*)&Ah[(rb + g) * LDK + 2 * t + 8];
            af[mi][3] = *(const unsigned*)&Ah[(rb + g + 8) * LDK + 2 * t + 8];
        }
#pragma unroll
        for (int nj = 0; nj < 4; nj++) {
            int cb = wn * 32 + nj * 8 + g;
            unsigned b0 = *(const unsigned*)&Bh[cb * LDK + 2 * t];
            unsigned b1 = *(const unsigned*)&Bh[cb * LDK + 2 * t + 8];
#pragma unroll
            for (int mi = 0; mi < 4; mi++) mma16816(acc[mi][nj], af[mi], b0, b1);
        }
#pragma unroll
        for (int nj = 0; nj < 4; nj++) {
            int cb = wn * 32 + nj * 8 + g;
            unsigned b0 = *(const unsigned*)&Bl[cb * LDK + 2 * t];
            unsigned b1 = *(const unsigned*)&Bl[cb * LDK + 2 * t + 8];
#pragma unroll
            for (int mi = 0; mi < 4; mi++) mma16816(acc[mi][nj], af[mi], b0, b1);
        }
#pragma unroll
        for (int mi = 0; mi < 4; mi++) {
            int rb = wm * 64 + mi * 16;
            af[mi][0] = *(const unsigned*)&Al[(rb + g) * LDK + 2 * t];
            af[mi][1] = *(const unsigned*)&Al[(rb + g + 8) * LDK + 2 * t];
            af[mi][2] = *(const unsigned*)&Al[(rb + g) * LDK + 2 * t + 8];
            af[mi][3] = *(const unsigned*)&Al[(rb + g + 8) * LDK + 2 * t + 8];
        }
#pragma unroll
        for (int nj = 0; nj < 4; nj++) {
            int cb = wn * 32 + nj * 8 + g;
            unsigned b0 = *(const unsigned*)&Bh[cb * LDK + 2 * t];
            unsigned b1 = *(const unsigned*)&Bh[cb * LDK + 2 * t + 8];
#pragma unroll
            for (int mi = 0; mi < 4; mi++) mma16816(acc[mi][nj], af[mi], b0, b1);
        }
        __syncthreads();
    }

#pragma unroll
    for (int mi = 0; mi < 4; mi++)
#pragma unroll
        for (int nj = 0; nj < 4; nj++) {
            int r = m0 + wm * 64 + mi * 16 + g;
            int col = n0 + wn * 32 + nj * 8 + 2 * t;
            *(float2*)&g_z[(size_t)r * 1024 + col] =
                make_float2(acc[mi][nj][0], acc[mi][nj][1]);
            *(float2*)&g_z[(size_t)(r + 8) * 1024 + col] =
                make_float2(acc[mi][nj][2], acc[mi][nj][3]);
        }
}

// ---------------------------------------------------------------------------
// K2a: LSTM gate epilogue -> h_new/c_new (d_out) + bf16 split of h (g_Hh/g_Hl)
// ---------------------------------------------------------------------------
__global__ __launch_bounds__(1024) void k2a_gates(
    const float* __restrict__ c0, const float* __restrict__ bl,
    float* __restrict__ out)
{
    int idx = blockIdx.x * 1024 + threadIdx.x;    // row*256 + u
    int row = idx >> 8, u = idx & 255;
    const float* zr = g_z + (size_t)row * 1024 + u;
    float zi = zr[0]   + bl[u];
    float zf = zr[256] + bl[256 + u];
    float zg = zr[512] + bl[512 + u];
    float zo = zr[768] + bl[768 + u];
    float cn = sigf(zf) * c0[idx] + sigf(zi) * tanhf(zg);
    float hn = sigf(zo) * tanhf(cn);
    out[O_C + idx] = cn;
    out[O_H + idx] = hn;
    __nv_bfloat16 hi = __float2bfloat16(hn);
    g_Hh[idx] = hi;
    g_Hl[idx] = __float2bfloat16(hn - __bfloat162float(hi));
}

// ---------------------------------------------------------------------------
// K2b: params = clip(h @ Wp + bp) -> g_params.  Same MMA engine, K=256.
// grid (32, 3): N padded to 384, store masked to 268.
// ---------------------------------------------------------------------------
__global__ __launch_bounds__(256, 2) void k2b_gemm(const float* __restrict__ bp)
{
    __shared__ __nv_bfloat16 smem[2 * 4 * 128 * LDK];
    const int tid = threadIdx.x;
    const int m0 = blockIdx.x * 128, n0 = blockIdx.y * 128;
    const int lane = tid & 31, wid = tid >> 5;
    const int wm = wid & 1, wn = wid >> 1;
    const int g = lane >> 2, t = lane & 3;

    float acc[4][4][4];
#pragma unroll
    for (int mi = 0; mi < 4; mi++)
#pragma unroll
        for (int nj = 0; nj < 4; nj++)
#pragma unroll
            for (int q = 0; q < 4; q++) acc[mi][nj][q] = 0.0f;

    const int row = tid >> 1, seg = tid & 1;
    const int soff = row * LDK + seg * 8;
    const int goffA = (m0 + row) * UU + seg * 8;
    const int goffB = (n0 + row) * UU + seg * 8;

    auto issue = [&](int s, int kb) {
        __nv_bfloat16* base = smem + s * (4 * 128 * LDK);
        cp16(base + 0 * 128 * LDK + soff, g_Hh + goffA + kb);
        cp16(base + 1 * 128 * LDK + soff, g_Hl + goffA + kb);
        cp16(base + 2 * 128 * LDK + soff, g_Wph + goffB + kb);
        cp16(base + 3 * 128 * LDK + soff, g_Wpl + goffB + kb);
        CP_COMMIT();
    };

    issue(0, 0);

    for (int it = 0; it < 16; it++) {
        if (it < 15) { issue((it + 1) & 1, 16 * (it + 1)); CP_WAIT(1); }
        else         { CP_WAIT(0); }
        __syncthreads();

        const __nv_bfloat16* Ah = smem + (it & 1) * (4 * 128 * LDK);
        const __nv_bfloat16* Al = Ah + 128 * LDK;
        const __nv_bfloat16* Bh = Ah + 2 * 128 * LDK;
        const __nv_bfloat16* Bl = Ah + 3 * 128 * LDK;

        unsigned af[4][4];
#pragma unroll
        for (int mi = 0; mi < 4; mi++) {
            int rb = wm * 64 + mi * 16;
            af[mi][0] = *(const unsigned*)&Ah[(rb + g) * LDK + 2 * t];
            af[mi][1] = *(const unsigned*)&Ah[(rb + g + 8) * LDK + 2 * t];
            af[mi][2] = *(const unsigned*)&Ah[(rb + g) * LDK + 2 * t + 8];
            af[mi][3] = *(const unsigned*)&Ah[(rb + g + 8) * LDK + 2 * t + 8];
        }
#pragma unroll
        for (int nj = 0; nj < 4; nj++) {
            int cb = wn * 32 + nj * 8 + g;
            unsigned b0 = *(const unsigned*)&Bh[cb * LDK + 2 * t];
            unsigned b1 = *(const unsigned*)&Bh[cb * LDK + 2 * t + 8];
#pragma unroll
            for (int mi = 0; mi < 4; mi++) mma16816(acc[mi][nj], af[mi], b0, b1);
        }
#pragma unroll
        for (int nj = 0; nj < 4; nj++) {
            int cb = wn * 32 + nj * 8 + g;
            unsigned b0 = *(const unsigned*)&Bl[cb * LDK + 2 * t];
            unsigned b1 = *(const unsigned*)&Bl[cb * LDK + 2 * t + 8];
#pragma unroll
            for (int mi = 0; mi < 4; mi++) mma16816(acc[mi][nj], af[mi], b0, b1);
        }
#pragma unroll
        for (int mi = 0; mi < 4; mi++) {
            int rb = wm * 64 + mi * 16;
            af[mi][0] = *(const unsigned*)&Al[(rb + g) * LDK + 2 * t];
            af[mi][1] = *(const unsigned*)&Al[(rb + g + 8) * LDK + 2 * t];
            af[mi][2] = *(const unsigned*)&Al[(rb + g) * LDK + 2 * t + 8];
            af[mi][3] = *(const unsigned*)&Al[(rb + g + 8) * LDK + 2 * t + 8];
        }
#pragma unroll
        for (int nj = 0; nj < 4; nj++) {
            int cb = wn * 32 + nj * 8 + g;
            unsigned b0 = *(const unsigned*)&Bh[cb * LDK + 2 * t];
            unsigned b1 = *(const unsigned*)&Bh[cb * LDK + 2 * t + 8];
#pragma unroll
            for (int mi = 0; mi < 4; mi++) mma16816(acc[mi][nj], af[mi], b0, b1);
        }
        __syncthreads();
    }

#pragma unroll
    for (int mi = 0; mi < 4; mi++)
#pragma unroll
        for (int nj = 0; nj < 4; nj++) {
            int col = n0 + wn * 32 + nj * 8 + 2 * t;
            if (col < PDIM) {           // col even, PDIM even -> col+1 < PDIM
                int r = m0 + wm * 64 + mi * 16 + g;
                float b0v = bp[col], b1v = bp[col + 1];
                *(float2*)&g_params[r * PDIM + col] = make_float2(
                    clipf(acc[mi][nj][0] + b0v), clipf(acc[mi][nj][1] + b1v));
                *(float2*)&g_params[(r + 8) * PDIM + col] = make_float2(
                    clipf(acc[mi][nj][2] + b0v), clipf(acc[mi][nj][3] + b1v));
            }
        }
}

// ---------------------------------------------------------------------------
// K3: per-sample addressing, BOTH heads in parallel (256 threads/CTA:
// tid<128 -> read head, tid>=128 -> write head), + read_vec + memory update.
// ---------------------------------------------------------------------------
__global__ __launch_bounds__(256) void k3_addr(
    const float* __restrict__ M,
    const float* __restrict__ w0p, const float* __restrict__ w1p,
    float* __restrict__ out)
{
    __shared__ float Ms[128 * 65];
    __shared__ float psm[PDIM];
    __shared__ float ks[2][64], er[64], ad[64];
    __shared__ float wgs[2][128], wrs[128], wws[128];
    __shared__ float redm[2][4], reds[2][4], redp[2][4];
    __shared__ float part[256];

    int b = blockIdx.x, tid = threadIdx.x;
    int h = tid >> 7, n = tid & 127;
    int lane = tid & 31, wid = tid >> 5, hw = wid & 3;

    // stage M: 2048 float4s over 256 threads
    const float4* M4 = (const float4*)(M + (size_t)b * NN * WW);
#pragma unroll
    for (int t = 0; t < 8; t++) {
        int idx4 = tid + t * 256;
        float4 v = M4[idx4];
        int r = idx4 >> 4, w0 = (idx4 & 15) * 4;
        float* p = &Ms[r * 65 + w0];
        p[0] = v.x; p[1] = v.y; p[2] = v.z; p[3] = v.w;
    }
    for (int i = tid; i < PDIM; i += 256) psm[i] = g_params[b * PDIM + i];
    __syncthreads();

    // row norm for slot n (each thread)
    float s = 0.0f;
#pragma unroll
    for (int w = 0; w < 64; w++) { float m = Ms[n * 65 + w]; s += m * m; }
    float minv = rsqrtf(fmaxf(s, EPSV));

    if (tid < 64)                    er[tid] = sigf(psm[2 * NPH + tid]);
    else if (tid >= 128 && tid < 192) ad[tid - 128] = tanhf(psm[2 * NPH + 64 + (tid - 128)]);

    int off = h * NPH;
    if (n < 64) ks[h][n] = tanhf(psm[off + n]);
    __syncthreads();

    // head scalars (redundant per thread within head)
    float sk = 0.0f;
#pragma unroll
    for (int w = 0; w < 64; w++) sk += ks[h][w] * ks[h][w];
    float kninv = rsqrtf(fmaxf(sk, EPSV));
    float beta = softplusf(psm[off + 64]);
    float g = sigf(psm[off + 65]);
    float e0 = psm[off + 66], e1 = psm[off + 67], e2 = psm[off + 68];
    float mx3 = fmaxf(e0, fmaxf(e1, e2));
    float x0 = expf(e0 - mx3), x1 = expf(e1 - mx3), x2 = expf(e2 - mx3);
    float sinv = 1.0f / (x0 + x1 + x2);
    float s0 = x0 * sinv, s1 = x1 * sinv, s2 = x2 * sinv;
    float gamma = softplusf(psm[off + 69]) + 1.0f;

    // content similarity + 128-wide softmax (4 warps per head)
    float dot = 0.0f;
#pragma unroll
    for (int w = 0; w < 64; w++) dot += ks[h][w] * Ms[n * 65 + w];
    float v = beta * (-dot * kninv * minv);

    float m = v;
#pragma unroll
    for (int o = 16; o; o >>= 1) m = fmaxf(m, __shfl_xor_sync(0xffffffffu, m, o));
    if (lane == 0) redm[h][hw] = m;
    __syncthreads();
    m = fmaxf(fmaxf(redm[h][0], redm[h][1]), fmaxf(redm[h][2], redm[h][3]));
    float e = expf(v - m);
    float ssum = e;
#pragma unroll
    for (int o = 16; o; o >>= 1) ssum += __shfl_xor_sync(0xffffffffu, ssum, o);
    if (lane == 0) reds[h][hw] = ssum;
    __syncthreads();
    ssum = reds[h][0] + reds[h][1] + reds[h][2] + reds[h][3];
    float wc = e / ssum;

    const float* prev = h ? w1p : w0p;
    float wg = g * wc + (1.0f - g) * prev[b * 128 + n];
    wgs[h][n] = wg;
    __syncthreads();

    float w_ = s0 * wg + s1 * wgs[h][(n + 127) & 127] + s2 * wgs[h][(n + 1) & 127];
    float wsh = exp2f(gamma * log2f(w_));    // w_ >= 0; w_==0 -> 0
    float s2sum = wsh;
#pragma unroll
    for (int o = 16; o; o >>= 1) s2sum += __shfl_xor_sync(0xffffffffu, s2sum, o);
    if (lane == 0) redp[h][hw] = s2sum;
    __syncthreads();
    s2sum = redp[h][0] + redp[h][1] + redp[h][2] + redp[h][3];
    float wf = wsh / s2sum;

    if (h == 0) { wrs[n] = wf; out[O_WR + (size_t)b * 128 + n] = wf; }
    else        { wws[n] = wf; out[O_WW + (size_t)b * 128 + n] = wf; }
    __syncthreads();

    // read_vec: 4-way split over n
    {
        int w = tid & 63, q = tid >> 6;
        float r = 0.0f;
#pragma unroll
        for (int i = 0; i < 32; i++) {
            int nn = q * 32 + i;
            r += wrs[nn] * Ms[nn * 65 + w];
        }
        part[tid] = r;
        __syncthreads();
        if (tid < 64)
            out[O_RV + (size_t)b * 64 + tid] =
                part[tid] + part[64 + tid] + part[128 + tid] + part[192 + tid];
    }

    // M update (256 threads, float4)
    float4* Mo = (float4*)(out + O_M + (size_t)b * NN * WW);
#pragma unroll
    for (int t = 0; t < 8; t++) {
        int idx4 = tid + t * 256;
        int r = idx4 >> 4, w0 = (idx4 & 15) * 4;
        float wn = wws[r];
        const float* p = &Ms[r * 65 + w0];
        float4 v4;
        v4.x = p[0] * (1.0f - wn * er[w0 + 0]) + wn * ad[w0 + 0];
        v4.y = p[1] * (1.0f - wn * er[w0 + 1]) + wn * ad[w0 + 1];
        v4.z = p[2] * (1.0f - wn * er[w0 + 2]) + wn * ad[w0 + 2];
        v4.w = p[3] * (1.0f - wn * er[w0 + 3]) + wn * ad[w0 + 3];
        Mo[idx4] = v4;
    }
}

// ---------------------------------------------------------------------------
// K4: out = clip([h_new, read_vec] @ W_o + b_o). 8 rows/CTA, split-k x4.
// ---------------------------------------------------------------------------
__global__ __launch_bounds__(256) void k4_out(
    const float* __restrict__ Wo, const float* __restrict__ bo,
    float* __restrict__ out)
{
    __shared__ float hs[8 * 320];
    __shared__ float red[4][8 * 64];
    int tid = threadIdx.x;
    int row0 = blockIdx.x * 8;

    for (int i = tid; i < 8 * 320; i += 256) {
        int r = i / 320, k = i - r * 320;
        hs[i] = (k < 256) ? out[O_H + (size_t)(row0 + r) * 256 + k]
                          : out[O_RV + (size_t)(row0 + r) * 64 + (k - 256)];
    }
    __syncthreads();

    int c = tid & 63, kq = tid >> 6;
    float acc[8];
#pragma unroll
    for (int j = 0; j < 8; j++) acc[j] = 0.0f;

    int kbeg = kq * 80;
    for (int k = kbeg; k < kbeg + 80; k += 4) {
        float w0 = Wo[(k + 0) * 64 + c];
        float w1 = Wo[(k + 1) * 64 + c];
        float w2 = Wo[(k + 2) * 64 + c];
        float w3 = Wo[(k + 3) * 64 + c];
#pragma unroll
        for (int j = 0; j < 8; j++) {
            float4 h4 = *(const float4*)&hs[j * 320 + k];
            acc[j] += h4.x * w0 + h4.y * w1 + h4.z * w2 + h4.w * w3;
        }
    }
#pragma unroll
    for (int j = 0; j < 8; j++) red[kq][j * 64 + c] = acc[j];
    __syncthreads();

#pragma unroll
    for (int j = kq * 2; j < kq * 2 + 2; j++) {
        float sres = red[0][j * 64 + c] + red[1][j * 64 + c]
                   + red[2][j * 64 + c] + red[3][j * 64 + c];
        out[O_OUT + (size_t)(row0 + j) * 64 + c] = clipf(sres + bo[c]);
    }
}

// ---------------------------------------------------------------------------
extern "C" void kernel_launch(void* const* d_in, const int* in_sizes, int n_in,
                              void* d_out, int out_size)
{
    const float* x   = (const float*)d_in[0];
    const float* h0  = (const float*)d_in[1];
    const float* c0  = (const float*)d_in[2];
    const float* rv0 = (const float*)d_in[3];
    const float* w0p = (const float*)d_in[4];
    const float* w1p = (const float*)d_in[5];
    const float* M   = (const float*)d_in[6];
    const float* Wk  = (const float*)d_in[7];
    const float* Wr  = (const float*)d_in[8];
    const float* bl  = (const float*)d_in[9];
    const float* Wp  = (const float*)d_in[10];
    const float* bp  = (const float*)d_in[11];
    const float* Wo  = (const float*)d_in[12];
    const float* bo  = (const float*)d_in[13];
    float* out = (float*)d_out;

    k0_act<<<BB * KD / 1024, 1024>>>(x, rv0, h0);
    k0_wt<<<dim3(32, 12), 256>>>(Wk, Wr);
    k0_wp<<<dim3(12, 8), 256>>>(Wp);
    k1_gemm<<<dim3(32, 8), 256>>>();
    k2a_gates<<<BB * UU / 1024, 1024>>>(c0, bl, out);
    k2b_gemm<<<dim3(32, 3), 256>>>(bp);
    k3_addr<<<BB, 256>>>(M, w0p, w1p, out);
    k4_out<<<BB / 8, 256>>>(Wo, bo, out);
}